// round 5
// baseline (speedup 1.0000x reference)
#include <cuda_runtime.h>
#include <mma.h>

using namespace nvcuda;

#define LDA 132   // leading dim for 64x128 fp32 buffers
#define LDT 68    // leading dim for vT (128x64)
#define LDP 68    // leading dim for per-head S/P buffers (64x64)
#define SCALE 0.17677669529663687f  // 1/sqrt(32)

__device__ float g_relbias[4 * 64 * 64];
__device__ float g_wts[65536];   // tf32-rounded [Wq 16384 | Wkv 32768 | Wo 16384]

__device__ __forceinline__ float rnd32(float x) {
    float r;
    asm("cvt.rna.tf32.f32 %0, %1;" : "=f"(r) : "f"(x));
    return r;
}

__global__ void relbias_kernel(const float* __restrict__ bias_table) {
    int idx = blockIdx.x * blockDim.x + threadIdx.x;
    if (idx < 4 * 64 * 64) {
        int h = idx >> 12;
        int n = (idx >> 6) & 63;
        int m = idx & 63;
        int r = ((n >> 3) - (m >> 3) + 7) * 15 + ((n & 7) - (m & 7) + 7);
        g_relbias[idx] = bias_table[r * 4 + h];
    }
}

__global__ void roundwts_kernel(const float* __restrict__ Wq,
                                const float* __restrict__ Wkv,
                                const float* __restrict__ Wo) {
    int idx = blockIdx.x * blockDim.x + threadIdx.x;
    if (idx < 16384)       g_wts[idx] = rnd32(Wq[idx]);
    else if (idx < 49152)  g_wts[idx] = rnd32(Wkv[idx - 16384]);
    else if (idx < 65536)  g_wts[idx] = rnd32(Wo[idx - 49152]);
}

using FragA = wmma::fragment<wmma::matrix_a, 16, 16, 8, wmma::precision::tf32, wmma::row_major>;
using FragB = wmma::fragment<wmma::matrix_b, 16, 16, 8, wmma::precision::tf32, wmma::col_major>;
using FragC = wmma::fragment<wmma::accumulator, 16, 16, 8, float>;

// COLUMN strip: NT vertical tiles at row-tiles mi0.., column-tile ni.
// All operands assumed pre-rounded to tf32 values.
template <int NT, int KTOT>
__device__ __forceinline__ void gemm_colstrip(const float* __restrict__ A, int lda,
                                              const float* __restrict__ Bt, int ldb,
                                              float* __restrict__ C, int ldc,
                                              int mi0, int ni) {
    FragC acc[NT];
#pragma unroll
    for (int t = 0; t < NT; t++) wmma::fill_fragment(acc[t], 0.0f);
#pragma unroll
    for (int k = 0; k < KTOT; k += 8) {
        FragB b;
        wmma::load_matrix_sync(b, Bt + k + ni * 16 * ldb, ldb);
#pragma unroll
        for (int t = 0; t < NT; t++) {
            FragA a;
            wmma::load_matrix_sync(a, A + (mi0 + t) * 16 * lda + k, lda);
            wmma::mma_sync(acc[t], a, b, acc[t]);
        }
    }
#pragma unroll
    for (int t = 0; t < NT; t++)
        wmma::store_matrix_sync(C + (mi0 + t) * 16 * ldc + ni * 16, acc[t], ldc, wmma::mem_row_major);
}

// ROW strip: NT horizontal tiles at row-tile mi, col-tiles ni0..
// RC: round accumulator to tf32 before store (when output feeds another GEMM).
template <int NT, int KTOT, bool RC>
__device__ __forceinline__ void gemm_rowstrip(const float* __restrict__ A, int lda,
                                              const float* __restrict__ Bt, int ldb,
                                              float* __restrict__ C, int ldc,
                                              int mi, int ni0) {
    FragC acc[NT];
#pragma unroll
    for (int t = 0; t < NT; t++) wmma::fill_fragment(acc[t], 0.0f);
#pragma unroll
    for (int k = 0; k < KTOT; k += 8) {
        FragA a;
        wmma::load_matrix_sync(a, A + mi * 16 * lda + k, lda);
#pragma unroll
        for (int t = 0; t < NT; t++) {
            FragB b;
            wmma::load_matrix_sync(b, Bt + k + (ni0 + t) * 16 * ldb, ldb);
            wmma::mma_sync(acc[t], a, b, acc[t]);
        }
    }
#pragma unroll
    for (int t = 0; t < NT; t++) {
        if (RC) {
#pragma unroll
            for (int i = 0; i < acc[t].num_elements; i++) acc[t].x[i] = rnd32(acc[t].x[i]);
        }
        wmma::store_matrix_sync(C + mi * 16 * ldc + (ni0 + t) * 16, acc[t], ldc, wmma::mem_row_major);
    }
}

// smem layout (floats):
//  [0      .. 17408)  sQ 64xLDA @0 / sKV 64xLDA @8448 | reused: sS (4 x 64xLDP = 17408)
//  [17408  .. 25856)  sQH  64xLDA  qh  | later x (attn out)
//  [25856  .. 34304)  sK   64xLDA  k   | later final out staging
//  [34304  .. 43008)  sVT  128xLDT v transposed
//  [43008  .. 47104)  sM   64x64   mask
#define SMEM_FLOATS 47104

__global__ void __launch_bounds__(512, 1)
win_attn_kernel(const float* __restrict__ q, const float* __restrict__ kv,
                const float* __restrict__ mask,
                const float* __restrict__ bq, const float* __restrict__ bkv,
                const float* __restrict__ bo,
                float* __restrict__ out) {
    extern __shared__ float smf[];
    float* sQ  = smf;
    float* sKV = smf + 8448;
    float* sQH = smf + 17408;
    float* sK  = smf + 25856;
    float* sVT = smf + 34304;
    float* sM  = smf + 43008;
    float* sS  = smf;          // overlaps sQ+sKV; valid after projections

    const float* gWq = g_wts;
    const float* gWk = g_wts + 16384;
    const float* gWv = g_wts + 32768;
    const float* gWo = g_wts + 49152;

    const int b = blockIdx.x;
    const int tid = threadIdx.x;
    const int w = tid >> 5;
    const int lane = tid & 31;

    // ---- load q, kv (rounded to tf32 at rest), mask ----
    const float4* q4 = (const float4*)(q + (size_t)b * 8192);
    const float4* kv4 = (const float4*)(kv + (size_t)b * 8192);
    for (int i = tid; i < 2048; i += 512) {
        int row = i >> 5, c4 = i & 31;
        float4 vq = q4[i];
        vq.x = rnd32(vq.x); vq.y = rnd32(vq.y); vq.z = rnd32(vq.z); vq.w = rnd32(vq.w);
        *(float4*)(sQ + row * LDA + c4 * 4) = vq;
        float4 vk = kv4[i];
        vk.x = rnd32(vk.x); vk.y = rnd32(vk.y); vk.z = rnd32(vk.z); vk.w = rnd32(vk.w);
        *(float4*)(sKV + row * LDA + c4 * 4) = vk;
    }
    const float4* m4 = (const float4*)(mask + (size_t)(b & 4095) * 4096);
    for (int i = tid; i < 1024; i += 512) ((float4*)sM)[i] = m4[i];
    __syncthreads();

    // ---- projections (16 warps) ----
    gemm_colstrip<2, 128>(sQ, LDA, gWq, 128, sQH, LDA, (w >> 3) * 2, w & 7);
    gemm_colstrip<2, 128>(sKV, LDA, gWk, 128, sK, LDA, (w >> 3) * 2, w & 7);
    gemm_rowstrip<2, 128, false>(gWv, 128, sKV, LDA, sVT, LDT, w >> 1, (w & 1) * 2);
    __syncthreads();

    // ---- biases (+scale for qh), round to tf32 at rest ----
    for (int i = tid; i < 8192; i += 512) {
        int row = i >> 7, c = i & 127;
        sQH[row * LDA + c] = rnd32((sQH[row * LDA + c] + bq[c]) * SCALE);
        sK[row * LDA + c] = rnd32(sK[row * LDA + c] + bkv[c]);
    }
    for (int i = tid; i < 8192; i += 512) {
        int cr = i >> 6, n = i & 63;
        sVT[cr * LDT + n] = rnd32(sVT[cr * LDT + n] + bkv[128 + cr]);
    }
    __syncthreads();

    // ---- attention: all 4 heads concurrently (4 warps per head) ----
    const int h = w >> 2;
    const int sub = w & 3;
    float* Ph = sS + h * 64 * LDP;

    // S_h = qh_h @ k_h^T (K=32)
    gemm_rowstrip<4, 32, false>(sQH + h * 32, LDA, sK + h * 32, LDA, Ph, LDP, sub, 0);
    __syncthreads();

    // softmax: warp owns 16 rows of its head; writes P rounded to tf32
    {
        const float* rb = g_relbias + h * 4096;
#pragma unroll
        for (int rr = 0; rr < 16; rr++) {
            int n = sub * 16 + rr;
            float l0 = Ph[n * LDP + lane] + rb[n * 64 + lane] + sM[n * 64 + lane];
            float l1 = Ph[n * LDP + lane + 32] + rb[n * 64 + lane + 32] + sM[n * 64 + lane + 32];
            float mx = fmaxf(l0, l1);
#pragma unroll
            for (int o = 16; o; o >>= 1) mx = fmaxf(mx, __shfl_xor_sync(0xffffffffu, mx, o));
            float e0 = __expf(l0 - mx);
            float e1 = __expf(l1 - mx);
            float s = e0 + e1;
#pragma unroll
            for (int o = 16; o; o >>= 1) s += __shfl_xor_sync(0xffffffffu, s, o);
            float inv = 1.0f / s;
            Ph[n * LDP + lane] = rnd32(e0 * inv);
            Ph[n * LDP + lane + 32] = rnd32(e1 * inv);
        }
    }
    __syncthreads();

    // x_h = P_h @ v_h (K=64), rounded accumulators -> sQH cols h*32..
    gemm_rowstrip<2, 64, true>(Ph, LDP, sVT + h * 32 * LDT, LDT, sQH + h * 32, LDA, sub, 0);
    __syncthreads();

    // ---- out = x @ Wo^T + bo ----
    gemm_colstrip<2, 128>(sQH, LDA, gWo, 128, sK, LDA, (w >> 3) * 2, w & 7);
    __syncthreads();

    const float4* bo4 = (const float4*)bo;
    float4* out4 = (float4*)out + (size_t)b * 2048;
    for (int i = tid; i < 2048; i += 512) {
        int row = i >> 5, c4 = i & 31;
        float4 v = *(const float4*)(sK + row * LDA + c4 * 4);
        float4 bb = bo4[c4];
        v.x += bb.x; v.y += bb.y; v.z += bb.z; v.w += bb.w;
        out4[i] = v;
    }
}

extern "C" void kernel_launch(void* const* d_in, const int* in_sizes, int n_in,
                              void* d_out, int out_size) {
    const float* q          = (const float*)d_in[0];
    const float* kv         = (const float*)d_in[1];
    const float* mask       = (const float*)d_in[2];
    const float* Wq         = (const float*)d_in[3];
    const float* bq         = (const float*)d_in[4];
    const float* Wkv        = (const float*)d_in[5];
    const float* bkv        = (const float*)d_in[6];
    const float* Wo         = (const float*)d_in[7];
    const float* bo         = (const float*)d_in[8];
    const float* bias_table = (const float*)d_in[9];
    float* out = (float*)d_out;

    relbias_kernel<<<64, 256>>>(bias_table);
    roundwts_kernel<<<256, 256>>>(Wq, Wkv, Wo);

    size_t smem = (size_t)SMEM_FLOATS * sizeof(float);
    cudaFuncSetAttribute(win_attn_kernel, cudaFuncAttributeMaxDynamicSharedMemorySize, (int)smem);
    win_attn_kernel<<<8192, 512, smem>>>(q, kv, mask, bq, bkv, bo, out);
}

// round 6
// speedup vs baseline: 1.0194x; 1.0194x over previous
#include <cuda_runtime.h>
#include <mma.h>

using namespace nvcuda;

#define SCALE 0.17677669529663687f  // 1/sqrt(32)

__device__ float g_relbias[4 * 64 * 64];
__device__ float g_wts[65536];   // tf32-rounded [Wq 16384 | Wk 16384 | Wv 16384 | Wo 16384]
__device__ float g_qh[67108864]; // [8192][64][128] scaled+biased+rounded
__device__ float g_k [67108864];
__device__ float g_v [67108864];

__device__ __forceinline__ float rnd32(float x) {
    float r;
    asm("cvt.rna.tf32.f32 %0, %1;" : "=f"(r) : "f"(x));
    return r;
}

__global__ void relbias_kernel(const float* __restrict__ bias_table) {
    int idx = blockIdx.x * blockDim.x + threadIdx.x;
    if (idx < 4 * 64 * 64) {
        int h = idx >> 12;
        int n = (idx >> 6) & 63;
        int m = idx & 63;
        int r = ((n >> 3) - (m >> 3) + 7) * 15 + ((n & 7) - (m & 7) + 7);
        g_relbias[idx] = bias_table[r * 4 + h];
    }
}

__global__ void roundwts_kernel(const float* __restrict__ Wq,
                                const float* __restrict__ Wkv,
                                const float* __restrict__ Wo) {
    int idx = blockIdx.x * blockDim.x + threadIdx.x;
    if (idx < 16384)       g_wts[idx] = rnd32(Wq[idx]);
    else if (idx < 49152)  g_wts[idx] = rnd32(Wkv[idx - 16384]);
    else if (idx < 65536)  g_wts[idx] = rnd32(Wo[idx - 49152]);
}

using FragA  = wmma::fragment<wmma::matrix_a, 16, 16, 8, wmma::precision::tf32, wmma::row_major>;
using FragB  = wmma::fragment<wmma::matrix_b, 16, 16, 8, wmma::precision::tf32, wmma::col_major>;
using FragBR = wmma::fragment<wmma::matrix_b, 16, 16, 8, wmma::precision::tf32, wmma::row_major>;
using FragC  = wmma::fragment<wmma::accumulator, 16, 16, 8, float>;

// ============================ Kernel 1: projections ============================
// CTA computes a 256x128 output tile: out = A(256x128) @ W^T(128x128) (+bias,scale,round)
// grid: [0,2048) -> qh ; [2048,6144) -> kv: mtile=(t>>1), nt=(t&1) (0->k, 1->v)
__global__ void __launch_bounds__(512, 1)
proj_kernel(const float* __restrict__ q, const float* __restrict__ kv,
            const float* __restrict__ bq, const float* __restrict__ bkv) {
    extern __shared__ float sm[];
    float* sA = sm;              // 256 x 132
    float* sW = sm + 256 * 132;  // 128 x 132

    const int cta = blockIdx.x;
    const int tid = threadIdx.x;
    const int w = tid >> 5;

    const float* src;
    const float* Wg;
    float* dst;
    const float* bias;
    float scl;
    int mtile;
    if (cta < 2048) {
        mtile = cta; src = q; Wg = g_wts; dst = g_qh; bias = bq; scl = SCALE;
    } else {
        int t = cta - 2048;
        mtile = t >> 1;
        int nt = t & 1;
        src = kv;
        Wg = g_wts + 16384 + nt * 16384;
        dst = nt ? g_v : g_k;
        bias = bkv + nt * 128;
        scl = 1.0f;
    }

    // stage A (rounded to tf32) and W (pre-rounded)
    const float4* s4 = (const float4*)(src + (size_t)mtile * 32768);
    for (int i = tid; i < 8192; i += 512) {
        float4 v = s4[i];
        v.x = rnd32(v.x); v.y = rnd32(v.y); v.z = rnd32(v.z); v.w = rnd32(v.w);
        int row = i >> 5, c4 = i & 31;
        *(float4*)(sA + row * 132 + c4 * 4) = v;
    }
    const float4* w4 = (const float4*)Wg;
    for (int i = tid; i < 4096; i += 512) {
        int row = i >> 5, c4 = i & 31;
        *(float4*)(sW + row * 132 + c4 * 4) = w4[i];
    }
    __syncthreads();

    // 16 warps: rp = w>>1 -> row-tiles {rp*2, rp*2+1}; ch = w&1 -> col-tiles ch*4..+3
    const int rp = w >> 1;
    const int ch = w & 1;
    FragC acc[2][4];
#pragma unroll
    for (int t = 0; t < 2; t++)
#pragma unroll
        for (int j = 0; j < 4; j++) wmma::fill_fragment(acc[t][j], 0.0f);

#pragma unroll
    for (int k = 0; k < 128; k += 8) {
        FragA a[2];
#pragma unroll
        for (int t = 0; t < 2; t++)
            wmma::load_matrix_sync(a[t], sA + (rp * 2 + t) * 16 * 132 + k, 132);
        FragB bfr[4];
#pragma unroll
        for (int j = 0; j < 4; j++)
            wmma::load_matrix_sync(bfr[j], sW + k + (ch * 4 + j) * 16 * 132, 132);
#pragma unroll
        for (int t = 0; t < 2; t++)
#pragma unroll
            for (int j = 0; j < 4; j++)
                wmma::mma_sync(acc[t][j], a[t], bfr[j], acc[t][j]);
    }
    __syncthreads();  // done reading sA -> reuse as C staging

#pragma unroll
    for (int t = 0; t < 2; t++)
#pragma unroll
        for (int j = 0; j < 4; j++)
            wmma::store_matrix_sync(sA + (rp * 2 + t) * 16 * 132 + (ch * 4 + j) * 16,
                                    acc[t][j], 132, wmma::mem_row_major);
    __syncthreads();

    // epilogue: bias (+scale for qh), round, write
    const float4* b4 = (const float4*)bias;
    float4* d4 = (float4*)(dst + (size_t)mtile * 32768);
    for (int i = tid; i < 8192; i += 512) {
        int row = i >> 5, c4 = i & 31;
        float4 v = *(const float4*)(sA + row * 132 + c4 * 4);
        float4 bb = b4[c4];
        v.x = rnd32((v.x + bb.x) * scl);
        v.y = rnd32((v.y + bb.y) * scl);
        v.z = rnd32((v.z + bb.z) * scl);
        v.w = rnd32((v.w + bb.w) * scl);
        d4[i] = v;
    }
}

// ============================ Kernel 2: attention + out-proj ============================

// ROW strip, col-major B: NT tiles at row-tile mi, col-tiles ni0..
template <int NT, int KTOT>
__device__ __forceinline__ void gemm_rowstrip(const float* __restrict__ A, int lda,
                                              const float* __restrict__ Bt, int ldb,
                                              float* __restrict__ C, int ldc,
                                              int mi, int ni0) {
    FragC acc[NT];
#pragma unroll
    for (int t = 0; t < NT; t++) wmma::fill_fragment(acc[t], 0.0f);
#pragma unroll
    for (int k = 0; k < KTOT; k += 8) {
        FragA a;
        wmma::load_matrix_sync(a, A + mi * 16 * lda + k, lda);
#pragma unroll
        for (int t = 0; t < NT; t++) {
            FragB b;
            wmma::load_matrix_sync(b, Bt + k + (ni0 + t) * 16 * ldb, ldb);
            wmma::mma_sync(acc[t], a, b, acc[t]);
        }
    }
#pragma unroll
    for (int t = 0; t < NT; t++)
        wmma::store_matrix_sync(C + mi * 16 * ldc + (ni0 + t) * 16, acc[t], ldc, wmma::mem_row_major);
}

// ROW strip, ROW-major B (for PV: B = v[m][d]); rounds accumulators before store.
template <int NT, int KTOT>
__device__ __forceinline__ void gemm_pv(const float* __restrict__ A, int lda,
                                        const float* __restrict__ Bt, int ldb,
                                        float* __restrict__ C, int ldc,
                                        int mi, int ni0) {
    FragC acc[NT];
#pragma unroll
    for (int t = 0; t < NT; t++) wmma::fill_fragment(acc[t], 0.0f);
#pragma unroll
    for (int k = 0; k < KTOT; k += 8) {
        FragA a;
        wmma::load_matrix_sync(a, A + mi * 16 * lda + k, lda);
#pragma unroll
        for (int t = 0; t < NT; t++) {
            FragBR b;
            wmma::load_matrix_sync(b, Bt + k * ldb + (ni0 + t) * 16, ldb);
            wmma::mma_sync(acc[t], a, b, acc[t]);
        }
    }
#pragma unroll
    for (int t = 0; t < NT; t++) {
#pragma unroll
        for (int i = 0; i < acc[t].num_elements; i++) acc[t].x[i] = rnd32(acc[t].x[i]);
        wmma::store_matrix_sync(C + mi * 16 * ldc + (ni0 + t) * 16, acc[t], ldc, wmma::mem_row_major);
    }
}

// COLUMN strip (B = global weight, col-major view)
template <int NT, int KTOT>
__device__ __forceinline__ void gemm_colstrip(const float* __restrict__ A, int lda,
                                              const float* __restrict__ Bt, int ldb,
                                              float* __restrict__ C, int ldc,
                                              int mi0, int ni) {
    FragC acc[NT];
#pragma unroll
    for (int t = 0; t < NT; t++) wmma::fill_fragment(acc[t], 0.0f);
#pragma unroll
    for (int k = 0; k < KTOT; k += 8) {
        FragB b;
        wmma::load_matrix_sync(b, Bt + k + ni * 16 * ldb, ldb);
#pragma unroll
        for (int t = 0; t < NT; t++) {
            FragA a;
            wmma::load_matrix_sync(a, A + (mi0 + t) * 16 * lda + k, lda);
            wmma::mma_sync(acc[t], a, b, acc[t]);
        }
    }
#pragma unroll
    for (int t = 0; t < NT; t++)
        wmma::store_matrix_sync(C + (mi0 + t) * 16 * ldc + ni * 16, acc[t], ldc, wmma::mem_row_major);
}

// smem (floats): sQH 64x132 @0 (later x) | sK 64x132 @8448 (later out) | sV 64x132 @16896
//                sM 64x64 @25344 | sS 4 x 64x68 @29440  -> total 46848 floats (187KB)
#define SMEM2_FLOATS 46848

__global__ void __launch_bounds__(512, 1)
attn_kernel(const float* __restrict__ mask, const float* __restrict__ bo,
            float* __restrict__ out) {
    extern __shared__ float smf[];
    float* sQH = smf;
    float* sK  = smf + 8448;
    float* sV  = smf + 16896;
    float* sM  = smf + 25344;
    float* sS  = smf + 29440;

    const int b = blockIdx.x;
    const int tid = threadIdx.x;
    const int w = tid >> 5;
    const int lane = tid & 31;

    // stage qh, k, v, mask
    const float4* a4 = (const float4*)(g_qh + (size_t)b * 8192);
    const float4* k4 = (const float4*)(g_k + (size_t)b * 8192);
    const float4* v4 = (const float4*)(g_v + (size_t)b * 8192);
    for (int i = tid; i < 2048; i += 512) {
        int row = i >> 5, c4 = i & 31;
        *(float4*)(sQH + row * 132 + c4 * 4) = a4[i];
        *(float4*)(sK + row * 132 + c4 * 4) = k4[i];
        *(float4*)(sV + row * 132 + c4 * 4) = v4[i];
    }
    const float4* m4 = (const float4*)(mask + (size_t)(b & 4095) * 4096);
    for (int i = tid; i < 1024; i += 512) ((float4*)sM)[i] = m4[i];
    __syncthreads();

    // S_h = qh_h @ k_h^T  (K=32): 4 warps per head
    const int h = w >> 2;
    const int sub = w & 3;
    float* Ph = sS + h * 64 * 68;
    gemm_rowstrip<4, 32>(sQH + h * 32, 132, sK + h * 32, 132, Ph, 68, sub, 0);
    __syncthreads();

    // softmax (qh already scaled): warp owns 16 rows of its head
    {
        const float* rb = g_relbias + h * 4096;
#pragma unroll
        for (int rr = 0; rr < 16; rr++) {
            int n = sub * 16 + rr;
            float l0 = Ph[n * 68 + lane] + rb[n * 64 + lane] + sM[n * 64 + lane];
            float l1 = Ph[n * 68 + lane + 32] + rb[n * 64 + lane + 32] + sM[n * 64 + lane + 32];
            float mx = fmaxf(l0, l1);
#pragma unroll
            for (int o = 16; o; o >>= 1) mx = fmaxf(mx, __shfl_xor_sync(0xffffffffu, mx, o));
            float e0 = __expf(l0 - mx);
            float e1 = __expf(l1 - mx);
            float s = e0 + e1;
#pragma unroll
            for (int o = 16; o; o >>= 1) s += __shfl_xor_sync(0xffffffffu, s, o);
            float inv = 1.0f / s;
            Ph[n * 68 + lane] = rnd32(e0 * inv);
            Ph[n * 68 + lane + 32] = rnd32(e1 * inv);
        }
    }
    __syncthreads();

    // x_h = P_h @ v_h (K=64, B row-major), rounded -> overwrite sQH cols h*32..
    gemm_pv<2, 64>(Ph, 68, sV + h * 32, 132, sQH + h * 32, 132, sub, 0);
    __syncthreads();

    // out = x @ Wo^T
    gemm_colstrip<2, 128>(sQH, 132, g_wts + 49152, 128, sK, 132, (w >> 3) * 2, w & 7);
    __syncthreads();

    const float4* bo4 = (const float4*)bo;
    float4* out4 = (float4*)out + (size_t)b * 2048;
    for (int i = tid; i < 2048; i += 512) {
        int row = i >> 5, c4 = i & 31;
        float4 v = *(const float4*)(sK + row * 132 + c4 * 4);
        float4 bb = bo4[c4];
        v.x += bb.x; v.y += bb.y; v.z += bb.z; v.w += bb.w;
        out4[i] = v;
    }
}

extern "C" void kernel_launch(void* const* d_in, const int* in_sizes, int n_in,
                              void* d_out, int out_size) {
    const float* q          = (const float*)d_in[0];
    const float* kv         = (const float*)d_in[1];
    const float* mask       = (const float*)d_in[2];
    const float* Wq         = (const float*)d_in[3];
    const float* bq         = (const float*)d_in[4];
    const float* Wkv        = (const float*)d_in[5];
    const float* bkv        = (const float*)d_in[6];
    const float* Wo         = (const float*)d_in[7];
    const float* bo         = (const float*)d_in[8];
    const float* bias_table = (const float*)d_in[9];
    float* out = (float*)d_out;

    relbias_kernel<<<64, 256>>>(bias_table);
    roundwts_kernel<<<256, 256>>>(Wq, Wkv, Wo);

    size_t smem1 = (size_t)(256 * 132 + 128 * 132) * sizeof(float);
    cudaFuncSetAttribute(proj_kernel, cudaFuncAttributeMaxDynamicSharedMemorySize, (int)smem1);
    proj_kernel<<<6144, 512, smem1>>>(q, kv, bq, bkv);

    size_t smem2 = (size_t)SMEM2_FLOATS * sizeof(float);
    cudaFuncSetAttribute(attn_kernel, cudaFuncAttributeMaxDynamicSharedMemorySize, (int)smem2);
    attn_kernel<<<8192, 512, smem2>>>(mask, bo, out);
}